// round 3
// baseline (speedup 1.0000x reference)
#include <cuda_runtime.h>
#include <cstdint>
#include <math.h>

// Problem constants
#define BB 64
#define SS 64
#define TT 21
#define DD 512
#define VV 32000
#define BT (BB*TT)        // 1344
#define NTILE (VV/64)     // 500

// ---------------- static device scratch ----------------
__device__ float g_cat[BB*640];        // [encode_hidden | style_feature]
__device__ float g_inp2[BB*1024];      // [context | h]
__device__ float g_gates[BB*2048];
__device__ float g_c[BB*512];
__device__ float g_emb[BT*512];        // emb_table[decoder_input]
__device__ float g_xproj[BT*2048];     // emb @ W_ih_emb^T + b_ih + b_hh
__device__ float g_wcomb[2048*1024];   // [W_ih_ctx | W_hh]
__device__ float g_biassum[2048];
__device__ float g_E2[BB*SS*512];      // enc @ attn_W^T  (scores = E2 . h)
__device__ float g_outs[BT*512];       // LSTM hidden outputs
__device__ float g_pmax[BT*NTILE];
__device__ float g_psum[BT*NTILE];
__device__ float g_lab[BT];
__device__ float g_nll[BT];

// ---------------- tf32 mma helpers ----------------
__device__ __forceinline__ float f2tf32(float x) {
    unsigned int r;
    asm("cvt.rna.tf32.f32 %0, %1;" : "=r"(r) : "f"(x));
    return __uint_as_float(r);
}

__device__ __forceinline__ void mma_tf32(float* d,
    float a0, float a1, float a2, float a3, float b0, float b1)
{
    asm volatile(
        "mma.sync.aligned.m16n8k8.row.col.f32.tf32.tf32.f32 "
        "{%0,%1,%2,%3},{%4,%5,%6,%7},{%8,%9},{%0,%1,%2,%3};\n"
        : "+f"(d[0]), "+f"(d[1]), "+f"(d[2]), "+f"(d[3])
        : "r"(__float_as_uint(a0)), "r"(__float_as_uint(a1)),
          "r"(__float_as_uint(a2)), "r"(__float_as_uint(a3)),
          "r"(__float_as_uint(b0)), "r"(__float_as_uint(b1)));
}

// Load 64x32 tile (row-major, leading dim ld) from (row0, k0) into dst[k][m],
// converting to tf32. 256 threads, float4 LDG.
__device__ __forceinline__ void load_tile(float (*dst)[73],
    const float* __restrict__ src, int ld, int row0, int k0, int tid)
{
#pragma unroll
    for (int i = 0; i < 2; i++) {
        int e = tid + i * 256;
        int m = e >> 3, kq = (e & 7) * 4;
        float4 v = *reinterpret_cast<const float4*>(
            &src[(size_t)(row0 + m) * ld + k0 + kq]);
        dst[kq + 0][m] = f2tf32(v.x);
        dst[kq + 1][m] = f2tf32(v.y);
        dst[kq + 2][m] = f2tf32(v.z);
        dst[kq + 3][m] = f2tf32(v.w);
    }
}

// ---------------- tf32 GEMM: C[M,N] = A[M,K] @ B[N,K]^T ----------------
// EPI=0: C = acc (+bias[n]) (+addf[m,n]) ; EPI=1: fused logsumexp partials
// (per-row max / sumexp over the 64-col tile) into g_pmax/g_psum.
// Block tile 64x64, 256 threads (8 warps: 4m x 2n), K chunk 32, K % 32 == 0.
template<int EPI>
__global__ void tf32_gemm(int K,
    const float* __restrict__ A, int lda,
    const float* __restrict__ B, int ldb,
    float* __restrict__ C, int ldc,
    const float* __restrict__ bias,
    const float* __restrict__ addf, int ldd)
{
    __shared__ float As[32][73];
    __shared__ float Bs[32][73];
    __shared__ float smax[2][64], ssum[2][64];
    const int bm = blockIdx.y * 64, bn = blockIdx.x * 64;
    const int tid = threadIdx.x, lane = tid & 31, warp = tid >> 5;
    const int wm = warp >> 1, wn = warp & 1;
    const int g = lane >> 2, tig = lane & 3;
    float acc[4][4] = {};

    for (int k0 = 0; k0 < K; k0 += 32) {
        load_tile(As, A, lda, bm, k0, tid);
        load_tile(Bs, B, ldb, bn, k0, tid);
        __syncthreads();
#pragma unroll
        for (int kk = 0; kk < 32; kk += 8) {
            float a0 = As[kk + tig][wm * 16 + g];
            float a1 = As[kk + tig][wm * 16 + g + 8];
            float a2 = As[kk + tig + 4][wm * 16 + g];
            float a3 = As[kk + tig + 4][wm * 16 + g + 8];
#pragma unroll
            for (int t4 = 0; t4 < 4; t4++) {
                int nn = wn * 32 + t4 * 8 + g;
                mma_tf32(acc[t4], a0, a1, a2, a3,
                         Bs[kk + tig][nn], Bs[kk + tig + 4][nn]);
            }
        }
        __syncthreads();
    }

    if (EPI == 0) {
#pragma unroll
        for (int t4 = 0; t4 < 4; t4++) {
            int n0 = bn + wn * 32 + t4 * 8 + tig * 2;
            int r0 = bm + wm * 16 + g, r1 = r0 + 8;
            float v00 = acc[t4][0], v01 = acc[t4][1];
            float v10 = acc[t4][2], v11 = acc[t4][3];
            if (bias) {
                float b0 = bias[n0], b1 = bias[n0 + 1];
                v00 += b0; v01 += b1; v10 += b0; v11 += b1;
            }
            if (addf) {
                v00 += addf[(size_t)r0 * ldd + n0];
                v01 += addf[(size_t)r0 * ldd + n0 + 1];
                v10 += addf[(size_t)r1 * ldd + n0];
                v11 += addf[(size_t)r1 * ldd + n0 + 1];
            }
            *reinterpret_cast<float2*>(&C[(size_t)r0 * ldc + n0]) = make_float2(v00, v01);
            *reinterpret_cast<float2*>(&C[(size_t)r1 * ldc + n0]) = make_float2(v10, v11);
        }
    } else {
        float vlo[8], vhi[8];
#pragma unroll
        for (int t4 = 0; t4 < 4; t4++) {
            int n0 = bn + wn * 32 + t4 * 8 + tig * 2;
            float b0 = bias[n0], b1 = bias[n0 + 1];
            vlo[t4 * 2]     = acc[t4][0] + b0;
            vlo[t4 * 2 + 1] = acc[t4][1] + b1;
            vhi[t4 * 2]     = acc[t4][2] + b0;
            vhi[t4 * 2 + 1] = acc[t4][3] + b1;
        }
        float mlo = -1e30f, mhi = -1e30f;
#pragma unroll
        for (int i = 0; i < 8; i++) { mlo = fmaxf(mlo, vlo[i]); mhi = fmaxf(mhi, vhi[i]); }
        mlo = fmaxf(mlo, __shfl_xor_sync(0xffffffffu, mlo, 1));
        mlo = fmaxf(mlo, __shfl_xor_sync(0xffffffffu, mlo, 2));
        mhi = fmaxf(mhi, __shfl_xor_sync(0xffffffffu, mhi, 1));
        mhi = fmaxf(mhi, __shfl_xor_sync(0xffffffffu, mhi, 2));
        float slo = 0.f, shi = 0.f;
#pragma unroll
        for (int i = 0; i < 8; i++) { slo += expf(vlo[i] - mlo); shi += expf(vhi[i] - mhi); }
        slo += __shfl_xor_sync(0xffffffffu, slo, 1);
        slo += __shfl_xor_sync(0xffffffffu, slo, 2);
        shi += __shfl_xor_sync(0xffffffffu, shi, 1);
        shi += __shfl_xor_sync(0xffffffffu, shi, 2);
        if (tig == 0) {
            smax[wn][wm * 16 + g]     = mlo; ssum[wn][wm * 16 + g]     = slo;
            smax[wn][wm * 16 + g + 8] = mhi; ssum[wn][wm * 16 + g + 8] = shi;
        }
        __syncthreads();
        if (tid < 64) {
            float m0 = smax[0][tid], m1 = smax[1][tid];
            float M = fmaxf(m0, m1);
            float S = ssum[0][tid] * expf(m0 - M) + ssum[1][tid] * expf(m1 - M);
            size_t row = bm + tid;
            g_pmax[row * NTILE + blockIdx.x] = M;
            g_psum[row * NTILE + blockIdx.x] = S;
        }
    }
}

// ---------------- fused pointwise(t-1) + attention(t) ----------------
__global__ void pwattn_kernel(const float* __restrict__ enc, int t)
{
    __shared__ float hs[512];
    __shared__ float sc[64];
    __shared__ float s_inv;
    const int b = blockIdx.x, tid = threadIdx.x;

    if (t > 0) {
        const int gb = b * 2048;
#pragma unroll
        for (int u = 0; u < 2; u++) {
            int j = tid + u * 256;
            float gi = g_gates[gb + j];
            float gf = g_gates[gb + 512 + j];
            float gg = g_gates[gb + 1024 + j];
            float go = g_gates[gb + 1536 + j];
            float c = g_c[b * 512 + j];
            float si = 1.f / (1.f + expf(-gi));
            float sf = 1.f / (1.f + expf(-gf));
            float so = 1.f / (1.f + expf(-go));
            c = sf * c + si * tanhf(gg);
            g_c[b * 512 + j] = c;
            float h = so * tanhf(c);
            g_outs[(size_t)(b * TT + (t - 1)) * 512 + j] = h;
            g_inp2[b * 1024 + 512 + j] = h;
            hs[j] = h;
        }
    } else {
        hs[tid]       = g_inp2[b * 1024 + 512 + tid];
        hs[tid + 256] = g_inp2[b * 1024 + 768 + tid];
    }
    __syncthreads();

    const int w = tid >> 5, lane = tid & 31;
    const float* E2b = g_E2 + (size_t)b * SS * 512;
    for (int s = w; s < SS; s += 8) {
        const float* er = E2b + (size_t)s * 512;
        float a = 0.f;
        for (int k = lane; k < 512; k += 32) a += hs[k] * er[k];
#pragma unroll
        for (int o = 16; o; o >>= 1) a += __shfl_xor_sync(0xffffffffu, a, o);
        if (lane == 0) sc[s] = a;
    }
    __syncthreads();

    if (w == 0) {
        float v0 = sc[lane], v1 = sc[lane + 32];
        float m = fmaxf(v0, v1);
#pragma unroll
        for (int o = 16; o; o >>= 1) m = fmaxf(m, __shfl_xor_sync(0xffffffffu, m, o));
        float e0 = expf(v0 - m), e1 = expf(v1 - m);
        float ssm = e0 + e1;
#pragma unroll
        for (int o = 16; o; o >>= 1) ssm += __shfl_xor_sync(0xffffffffu, ssm, o);
        sc[lane] = e0; sc[lane + 32] = e1;
        if (lane == 0) s_inv = 1.f / ssm;
    }
    __syncthreads();

    float inv = s_inv;
    const float* eb = enc + (size_t)b * SS * DD;
    for (int d = tid; d < DD; d += 256) {
        float a = 0.f;
#pragma unroll 8
        for (int s = 0; s < SS; s++) a += sc[s] * eb[(size_t)s * DD + d];
        g_inp2[b * 1024 + d] = a * inv;
    }
}

// final pointwise (produces outs[T-1])
__global__ void pw_final_kernel()
{
    const int b = blockIdx.x, j = threadIdx.x;
    const int gb = b * 2048;
    float gi = g_gates[gb + j];
    float gf = g_gates[gb + 512 + j];
    float gg = g_gates[gb + 1024 + j];
    float go = g_gates[gb + 1536 + j];
    float c = g_c[b * 512 + j];
    float si = 1.f / (1.f + expf(-gi));
    float sf = 1.f / (1.f + expf(-gf));
    float so = 1.f / (1.f + expf(-go));
    c = sf * c + si * tanhf(gg);
    float h = so * tanhf(c);
    g_outs[(size_t)(b * TT + TT - 1) * 512 + j] = h;
}

// ---------------- one-time prep ----------------
__global__ void prep_small_kernel(const float* __restrict__ eh, const float* __restrict__ st,
                                  const float* __restrict__ bih, const float* __restrict__ bhh)
{
    int i = blockIdx.x * blockDim.x + threadIdx.x;
    if (i < BB * 640) {
        int b = i / 640, j = i - b * 640;
        g_cat[i] = (j < 512) ? eh[b * 512 + j] : st[b * 512 + 384 + (j - 512)];
    } else if (i < BB * 640 + 2048) {
        int j = i - BB * 640;
        g_biassum[j] = bih[j] + bhh[j];
    } else if (i < BB * 640 + 2048 + BB * 512) {
        g_c[i - (BB * 640 + 2048)] = 0.f;
    }
}

__global__ void wcomb_kernel(const float* __restrict__ wih, const float* __restrict__ whh)
{
    int i = blockIdx.x * blockDim.x + threadIdx.x;
    int r = i >> 10, c = i & 1023;
    g_wcomb[i] = (c < 512) ? wih[(size_t)r * 1024 + c] : whh[(size_t)r * 512 + (c - 512)];
}

__global__ void embed_kernel(const int* __restrict__ di, const float* __restrict__ et)
{
    int row = blockIdx.x, tid = threadIdx.x;
    int idx = di[row];
    g_emb[(size_t)row * 512 + tid] = et[(size_t)idx * 512 + tid];
}

// ---------------- loss ----------------
__global__ void lablogit_kernel(const int* __restrict__ lab, const float* __restrict__ pw,
                                const float* __restrict__ pb)
{
    int gt = blockIdx.x * blockDim.x + threadIdx.x;
    int w = gt >> 5, lane = gt & 31;
    if (w >= BT) return;
    int l = lab[w];
    const float* o  = g_outs + (size_t)w * 512;
    const float* wr = pw + (size_t)l * 512;
    float a = 0.f;
    for (int k = lane; k < 512; k += 32) a += o[k] * wr[k];
#pragma unroll
    for (int off = 16; off; off >>= 1) a += __shfl_xor_sync(0xffffffffu, a, off);
    if (lane == 0) g_lab[w] = a + pb[l];
}

__global__ void loss_row_kernel(const int* __restrict__ lab)
{
    __shared__ float red[128];
    const int r = blockIdx.x, tid = threadIdx.x;
    const float* pm = g_pmax + (size_t)r * NTILE;
    const float* ps = g_psum + (size_t)r * NTILE;
    float m = -1e30f;
    for (int j = tid; j < NTILE; j += 128) m = fmaxf(m, pm[j]);
    red[tid] = m; __syncthreads();
    for (int s = 64; s; s >>= 1) { if (tid < s) red[tid] = fmaxf(red[tid], red[tid + s]); __syncthreads(); }
    float M = red[0]; __syncthreads();
    float se = 0.f;
    for (int j = tid; j < NTILE; j += 128) se += ps[j] * expf(pm[j] - M);
    red[tid] = se; __syncthreads();
    for (int s = 64; s; s >>= 1) { if (tid < s) red[tid] += red[tid + s]; __syncthreads(); }
    if (tid == 0) {
        float lse = M + logf(red[0]);
        int l = lab[r];
        g_nll[r] = (l > 0) ? (lse - g_lab[r]) : 0.f;
    }
}

__global__ void loss_final_kernel(const int* __restrict__ lab, float* __restrict__ out)
{
    __shared__ float red[64];
    const int b = threadIdx.x;
    float s = 0.f, cnt = 0.f;
    for (int t = 0; t < TT; t++) {
        int r = b * TT + t;
        s += g_nll[r];
        cnt += (lab[r] > 0) ? 1.f : 0.f;
    }
    red[b] = s / (cnt + 1e-6f);
    __syncthreads();
    if (b == 0) {
        float a = 0.f;
        for (int i = 0; i < 64; i++) a += red[i];
        out[0] = a / 64.f;
    }
}

// ---------------- host launcher ----------------
extern "C" void kernel_launch(void* const* d_in, const int* in_sizes, int n_in,
                              void* d_out, int out_size)
{
    const float* encode_hidden = (const float*)d_in[0];
    const float* encode_output = (const float*)d_in[1];
    const int*   seq_label     = (const int*)  d_in[3];
    const int*   decoder_input = (const int*)  d_in[4];
    const float* style_emb     = (const float*)d_in[5];
    const float* w_e2d         = (const float*)d_in[6];
    const float* b_e2d         = (const float*)d_in[7];
    const float* attn_W        = (const float*)d_in[8];
    const float* emb_table     = (const float*)d_in[9];
    const float* w_ih          = (const float*)d_in[10];
    const float* w_hh          = (const float*)d_in[11];
    const float* b_ih          = (const float*)d_in[12];
    const float* b_hh          = (const float*)d_in[13];
    const float* proj_w        = (const float*)d_in[14];
    const float* proj_b        = (const float*)d_in[15];
    float* out = (float*)d_out;

    float *p_cat, *p_inp2, *p_gates, *p_emb, *p_xproj, *p_wcomb, *p_biassum, *p_E2, *p_outs;
    cudaGetSymbolAddress((void**)&p_cat,     g_cat);
    cudaGetSymbolAddress((void**)&p_inp2,    g_inp2);
    cudaGetSymbolAddress((void**)&p_gates,   g_gates);
    cudaGetSymbolAddress((void**)&p_emb,     g_emb);
    cudaGetSymbolAddress((void**)&p_xproj,   g_xproj);
    cudaGetSymbolAddress((void**)&p_wcomb,   g_wcomb);
    cudaGetSymbolAddress((void**)&p_biassum, g_biassum);
    cudaGetSymbolAddress((void**)&p_E2,      g_E2);
    cudaGetSymbolAddress((void**)&p_outs,    g_outs);

    // one-time prep
    prep_small_kernel<<<424, 256>>>(encode_hidden, style_emb, b_ih, b_hh);
    wcomb_kernel<<<2048, 1024>>>(w_ih, w_hh);
    embed_kernel<<<BT, 512>>>(decoder_input, emb_table);

    // h0 = cat @ W_e2d^T + b  -> h half of inp2
    tf32_gemm<0><<<dim3(8, 1), 256>>>(640,
        p_cat, 640, w_e2d, 640, p_inp2 + 512, 1024, b_e2d, nullptr, 0);

    // xproj = emb @ W_ih_emb^T + (b_ih + b_hh)
    tf32_gemm<0><<<dim3(32, 21), 256>>>(512,
        p_emb, 512, w_ih + 512, 1024, p_xproj, 2048, p_biassum, nullptr, 0);

    // E2 = enc @ attn_W^T  (so scores = E2 . h, no per-step q GEMM)
    tf32_gemm<0><<<dim3(8, 64), 256>>>(512,
        encode_output, 512, attn_W, 512, p_E2, 512, nullptr, nullptr, 0);

    for (int t = 0; t < TT; t++) {
        // pointwise(t-1) fused with attention(t)
        pwattn_kernel<<<64, 256>>>(encode_output, t);
        // gates = [ctx|h] @ [W_ih_ctx|W_hh]^T + xproj[:, t, :]
        tf32_gemm<0><<<dim3(32, 1), 256>>>(1024,
            p_inp2, 1024, p_wcomb, 1024, p_gates, 2048, nullptr,
            p_xproj + (size_t)t * 2048, TT * 2048);
    }
    pw_final_kernel<<<64, 512>>>();

    // loss
    lablogit_kernel<<<168, 256>>>(seq_label, proj_w, proj_b);
    tf32_gemm<1><<<dim3(NTILE, 21), 256>>>(512,
        p_outs, 512, proj_w, 512, nullptr, 0, proj_b, nullptr, 0);
    loss_row_kernel<<<BT, 128>>>(seq_label);
    loss_final_kernel<<<1, 64>>>(seq_label, out);
}

// round 5
// speedup vs baseline: 1.1823x; 1.1823x over previous
#include <cuda_runtime.h>
#include <cstdint>
#include <math.h>

// Problem constants
#define BB 64
#define SS 64
#define TT 21
#define DD 512
#define VV 32000
#define BT (BB*TT)        // 1344
#define NTILE (VV/64)     // 500

// ---------------- static device scratch ----------------
__device__ float g_cat[BB*640];        // [encode_hidden | style_feature]
__device__ float g_inp2[BB*1024];      // [context | h]
__device__ float g_gates[BB*2048];
__device__ float g_c[BB*512];
__device__ float g_emb[BT*512];        // emb_table[decoder_input]
__device__ float g_xproj[BT*2048];     // emb @ W_ih_emb^T + b_ih + b_hh
__device__ float g_wcomb[2048*1024];   // [W_ih_ctx | W_hh]
__device__ float g_biassum[2048];
__device__ float g_E2[BB*SS*512];      // enc @ attn_W^T  (scores = E2 . h)
__device__ float g_outs[BT*512];       // LSTM hidden outputs
__device__ float g_pmax[BT*NTILE];
__device__ float g_psum[BT*NTILE];
__device__ float g_lab[BT];
__device__ float g_nll[BT];

// ---------------- packed f32x2 helpers (Blackwell FFMA2) ----------------
__device__ __forceinline__ double pk2(float lo, float hi) {
    double d;
    asm("mov.b64 %0, {%1, %2};" : "=d"(d) : "f"(lo), "f"(hi));
    return d;
}
__device__ __forceinline__ void upk2(double v, float& lo, float& hi) {
    asm("mov.b64 {%0, %1}, %2;" : "=f"(lo), "=f"(hi) : "d"(v));
}
__device__ __forceinline__ void fma2(double& d, double a, double b) {
    asm("fma.rn.f32x2 %0, %1, %2, %0;" : "+d"(d) : "d"(a), "d"(b));
}

// ---------------- generic tiled fp32 GEMM (f32x2 inner loop) ----------------
// C[M,N] (+)= A[M,K] @ op(B)  (+ bias[n]) (+ addf[m,n])
// TRANSB: B is (N,K) row-major; else B is (K,N) row-major.
// ATOMIC: atomicAdd into C (split-K; C pre-inited). kbeg = blockIdx.z*klen.
template<bool TRANSB, bool ATOMIC>
__global__ void gemm_kernel(int klen,
                            const float* __restrict__ A, int lda,
                            const float* __restrict__ B, int ldb,
                            float* __restrict__ C, int ldc,
                            const float* __restrict__ bias,
                            const float* __restrict__ addf, int ldd)
{
    __shared__ float As[32][68];
    __shared__ float Bs[32][68];
    const int bm = blockIdx.y * 64;
    const int bn = blockIdx.x * 64;
    const int kbeg = blockIdx.z * klen;
    const int tid = threadIdx.x;
    const int tm = (tid >> 4) << 2;
    const int tn = (tid & 15) << 2;
    double acc2[4][2] = {};

    for (int k0 = kbeg; k0 < kbeg + klen; k0 += 32) {
#pragma unroll
        for (int i = 0; i < 8; i++) {
            int e = tid + i * 256;
            int m = e >> 5, k = e & 31;
            As[k][m] = A[(size_t)(bm + m) * lda + k0 + k];
        }
        if (TRANSB) {
#pragma unroll
            for (int i = 0; i < 8; i++) {
                int e = tid + i * 256;
                int n = e >> 5, k = e & 31;
                Bs[k][n] = B[(size_t)(bn + n) * ldb + k0 + k];
            }
        } else {
#pragma unroll
            for (int i = 0; i < 8; i++) {
                int e = tid + i * 256;
                int k = e >> 6, n = e & 63;
                Bs[k][n] = B[(size_t)(k0 + k) * ldb + bn + n];
            }
        }
        __syncthreads();
#pragma unroll
        for (int k = 0; k < 32; k++) {
            float4 av = *reinterpret_cast<const float4*>(&As[k][tm]);
            float4 bv = *reinterpret_cast<const float4*>(&Bs[k][tn]);
            double b01 = pk2(bv.x, bv.y), b23 = pk2(bv.z, bv.w);
            double a0 = pk2(av.x, av.x), a1 = pk2(av.y, av.y);
            double a2 = pk2(av.z, av.z), a3 = pk2(av.w, av.w);
            fma2(acc2[0][0], a0, b01); fma2(acc2[0][1], a0, b23);
            fma2(acc2[1][0], a1, b01); fma2(acc2[1][1], a1, b23);
            fma2(acc2[2][0], a2, b01); fma2(acc2[2][1], a2, b23);
            fma2(acc2[3][0], a3, b01); fma2(acc2[3][1], a3, b23);
        }
        __syncthreads();
    }

    float acc[4][4];
#pragma unroll
    for (int i = 0; i < 4; i++) {
        upk2(acc2[i][0], acc[i][0], acc[i][1]);
        upk2(acc2[i][1], acc[i][2], acc[i][3]);
    }

    if (ATOMIC) {
#pragma unroll
        for (int i = 0; i < 4; i++) {
            size_t ro = (size_t)(bm + tm + i);
#pragma unroll
            for (int j = 0; j < 4; j++)
                atomicAdd(&C[ro * ldc + bn + tn + j], acc[i][j]);
        }
    } else {
#pragma unroll
        for (int i = 0; i < 4; i++) {
            size_t ro = (size_t)(bm + tm + i);
#pragma unroll
            for (int j = 0; j < 4; j++) {
                float v = acc[i][j];
                int n = bn + tn + j;
                if (bias) v += bias[n];
                if (addf) v += addf[ro * ldd + n];
                C[ro * ldc + n] = v;
            }
        }
    }
}

// ---------------- projection GEMM fused with per-tile logsumexp partials ----------------
// logits tile = outs[64,512] @ proj_w[64,512]^T + proj_b; emit per-row (max, sumexp).
__global__ void proj_lse_kernel(const float* __restrict__ Bw, const float* __restrict__ pb)
{
    __shared__ float As[32][68];
    __shared__ float Bs[32][68];
    const int bm = blockIdx.y * 64;
    const int bn = blockIdx.x * 64;
    const int tid = threadIdx.x;
    const int tm = (tid >> 4) << 2;
    const int tn = (tid & 15) << 2;
    double acc2[4][2] = {};

    for (int k0 = 0; k0 < 512; k0 += 32) {
#pragma unroll
        for (int i = 0; i < 8; i++) {
            int e = tid + i * 256;
            int m = e >> 5, k = e & 31;
            As[k][m] = g_outs[(size_t)(bm + m) * 512 + k0 + k];
        }
#pragma unroll
        for (int i = 0; i < 8; i++) {
            int e = tid + i * 256;
            int n = e >> 5, k = e & 31;
            Bs[k][n] = Bw[(size_t)(bn + n) * 512 + k0 + k];
        }
        __syncthreads();
#pragma unroll
        for (int k = 0; k < 32; k++) {
            float4 av = *reinterpret_cast<const float4*>(&As[k][tm]);
            float4 bv = *reinterpret_cast<const float4*>(&Bs[k][tn]);
            double b01 = pk2(bv.x, bv.y), b23 = pk2(bv.z, bv.w);
            double a0 = pk2(av.x, av.x), a1 = pk2(av.y, av.y);
            double a2 = pk2(av.z, av.z), a3 = pk2(av.w, av.w);
            fma2(acc2[0][0], a0, b01); fma2(acc2[0][1], a0, b23);
            fma2(acc2[1][0], a1, b01); fma2(acc2[1][1], a1, b23);
            fma2(acc2[2][0], a2, b01); fma2(acc2[2][1], a2, b23);
            fma2(acc2[3][0], a3, b01); fma2(acc2[3][1], a3, b23);
        }
        __syncthreads();
    }

    float acc[4][4];
#pragma unroll
    for (int i = 0; i < 4; i++) {
        upk2(acc2[i][0], acc[i][0], acc[i][1]);
        upk2(acc2[i][1], acc[i][2], acc[i][3]);
    }

    float bj[4];
#pragma unroll
    for (int j = 0; j < 4; j++) bj[j] = pb[bn + tn + j];
#pragma unroll
    for (int i = 0; i < 4; i++)
#pragma unroll
        for (int j = 0; j < 4; j++) acc[i][j] += bj[j];

    // per output-row reduction across the 16 threads of the row group
#pragma unroll
    for (int i = 0; i < 4; i++) {
        float m = fmaxf(fmaxf(acc[i][0], acc[i][1]), fmaxf(acc[i][2], acc[i][3]));
#pragma unroll
        for (int o = 8; o; o >>= 1) m = fmaxf(m, __shfl_xor_sync(0xffffffffu, m, o));
        float se = expf(acc[i][0] - m) + expf(acc[i][1] - m)
                 + expf(acc[i][2] - m) + expf(acc[i][3] - m);
#pragma unroll
        for (int o = 8; o; o >>= 1) se += __shfl_xor_sync(0xffffffffu, se, o);
        if ((tid & 15) == 0) {
            int row = bm + tm + i;
            g_pmax[(size_t)row * NTILE + blockIdx.x] = m;
            g_psum[(size_t)row * NTILE + blockIdx.x] = se;
        }
    }
}

// ---------------- fused pointwise(t-1) + attention(t) ----------------
__global__ void pwattn_kernel(const float* __restrict__ enc, int t)
{
    __shared__ float hs[512];
    __shared__ float sc[64];
    __shared__ float s_inv;
    const int b = blockIdx.x, tid = threadIdx.x;

    if (t > 0) {
        const int gb = b * 2048;
#pragma unroll
        for (int u = 0; u < 2; u++) {
            int j = tid + u * 256;
            float gi = g_gates[gb + j];
            float gf = g_gates[gb + 512 + j];
            float gg = g_gates[gb + 1024 + j];
            float go = g_gates[gb + 1536 + j];
            float c = g_c[b * 512 + j];
            float si = 1.f / (1.f + expf(-gi));
            float sf = 1.f / (1.f + expf(-gf));
            float so = 1.f / (1.f + expf(-go));
            c = sf * c + si * tanhf(gg);
            g_c[b * 512 + j] = c;
            float h = so * tanhf(c);
            g_outs[(size_t)(b * TT + (t - 1)) * 512 + j] = h;
            g_inp2[b * 1024 + 512 + j] = h;
            hs[j] = h;
        }
    } else {
        hs[tid]       = g_inp2[b * 1024 + 512 + tid];
        hs[tid + 256] = g_inp2[b * 1024 + 768 + tid];
    }
    __syncthreads();

    // init gates = xproj[:, t, :] for the split-K atomic GEMM
    {
        size_t xo = (size_t)(b * TT + t) * 2048;
#pragma unroll
        for (int i = 0; i < 8; i++)
            g_gates[b * 2048 + tid + i * 256] = g_xproj[xo + tid + i * 256];
    }

    const int w = tid >> 5, lane = tid & 31;
    const float* E2b = g_E2 + (size_t)b * SS * 512;
    for (int s = w; s < SS; s += 8) {
        const float* er = E2b + (size_t)s * 512;
        float a = 0.f;
        for (int k = lane; k < 512; k += 32) a += hs[k] * er[k];
#pragma unroll
        for (int o = 16; o; o >>= 1) a += __shfl_xor_sync(0xffffffffu, a, o);
        if (lane == 0) sc[s] = a;
    }
    __syncthreads();

    if (w == 0) {
        float v0 = sc[lane], v1 = sc[lane + 32];
        float m = fmaxf(v0, v1);
#pragma unroll
        for (int o = 16; o; o >>= 1) m = fmaxf(m, __shfl_xor_sync(0xffffffffu, m, o));
        float e0 = expf(v0 - m), e1 = expf(v1 - m);
        float ssm = e0 + e1;
#pragma unroll
        for (int o = 16; o; o >>= 1) ssm += __shfl_xor_sync(0xffffffffu, ssm, o);
        sc[lane] = e0; sc[lane + 32] = e1;
        if (lane == 0) s_inv = 1.f / ssm;
    }
    __syncthreads();

    float inv = s_inv;
    const float* eb = enc + (size_t)b * SS * DD;
    for (int d = tid; d < DD; d += 256) {
        float a = 0.f;
#pragma unroll 8
        for (int s = 0; s < SS; s++) a += sc[s] * eb[(size_t)s * DD + d];
        g_inp2[b * 1024 + d] = a * inv;
    }
}

// final pointwise (produces outs[T-1])
__global__ void pw_final_kernel()
{
    const int b = blockIdx.x, j = threadIdx.x;
    const int gb = b * 2048;
    float gi = g_gates[gb + j];
    float gf = g_gates[gb + 512 + j];
    float gg = g_gates[gb + 1024 + j];
    float go = g_gates[gb + 1536 + j];
    float c = g_c[b * 512 + j];
    float si = 1.f / (1.f + expf(-gi));
    float sf = 1.f / (1.f + expf(-gf));
    float so = 1.f / (1.f + expf(-go));
    c = sf * c + si * tanhf(gg);
    float h = so * tanhf(c);
    g_outs[(size_t)(b * TT + TT - 1) * 512 + j] = h;
}

// ---------------- one-time prep ----------------
__global__ void prep_small_kernel(const float* __restrict__ eh, const float* __restrict__ st,
                                  const float* __restrict__ bih, const float* __restrict__ bhh)
{
    int i = blockIdx.x * blockDim.x + threadIdx.x;
    if (i < BB * 640) {
        int b = i / 640, j = i - b * 640;
        g_cat[i] = (j < 512) ? eh[b * 512 + j] : st[b * 512 + 384 + (j - 512)];
    } else if (i < BB * 640 + 2048) {
        int j = i - BB * 640;
        g_biassum[j] = bih[j] + bhh[j];
    } else if (i < BB * 640 + 2048 + BB * 512) {
        g_c[i - (BB * 640 + 2048)] = 0.f;
    }
}

__global__ void wcomb_kernel(const float* __restrict__ wih, const float* __restrict__ whh)
{
    int i = blockIdx.x * blockDim.x + threadIdx.x;
    int r = i >> 10, c = i & 1023;
    g_wcomb[i] = (c < 512) ? wih[(size_t)r * 1024 + c] : whh[(size_t)r * 512 + (c - 512)];
}

__global__ void embed_kernel(const int* __restrict__ di, const float* __restrict__ et)
{
    int row = blockIdx.x, tid = threadIdx.x;
    int idx = di[row];
    g_emb[(size_t)row * 512 + tid] = et[(size_t)idx * 512 + tid];
}

// ---------------- loss ----------------
__global__ void lablogit_kernel(const int* __restrict__ lab, const float* __restrict__ pw,
                                const float* __restrict__ pb)
{
    int gt = blockIdx.x * blockDim.x + threadIdx.x;
    int w = gt >> 5, lane = gt & 31;
    if (w >= BT) return;
    int l = lab[w];
    const float* o  = g_outs + (size_t)w * 512;
    const float* wr = pw + (size_t)l * 512;
    float a = 0.f;
    for (int k = lane; k < 512; k += 32) a += o[k] * wr[k];
#pragma unroll
    for (int off = 16; off; off >>= 1) a += __shfl_xor_sync(0xffffffffu, a, off);
    if (lane == 0) g_lab[w] = a + pb[l];
}

__global__ void loss_row_kernel(const int* __restrict__ lab)
{
    __shared__ float red[128];
    const int r = blockIdx.x, tid = threadIdx.x;
    const float* pm = g_pmax + (size_t)r * NTILE;
    const float* ps = g_psum + (size_t)r * NTILE;
    float m = -1e30f;
    for (int j = tid; j < NTILE; j += 128) m = fmaxf(m, pm[j]);
    red[tid] = m; __syncthreads();
    for (int s = 64; s; s >>= 1) { if (tid < s) red[tid] = fmaxf(red[tid], red[tid + s]); __syncthreads(); }
    float M = red[0]; __syncthreads();
    float se = 0.f;
    for (int j = tid; j < NTILE; j += 128) se += ps[j] * expf(pm[j] - M);
    red[tid] = se; __syncthreads();
    for (int s = 64; s; s >>= 1) { if (tid < s) red[tid] += red[tid + s]; __syncthreads(); }
    if (tid == 0) {
        float lse = M + logf(red[0]);
        int l = lab[r];
        g_nll[r] = (l > 0) ? (lse - g_lab[r]) : 0.f;
    }
}

__global__ void loss_final_kernel(const int* __restrict__ lab, float* __restrict__ out)
{
    __shared__ float red[64];
    const int b = threadIdx.x;
    float s = 0.f, cnt = 0.f;
    for (int t = 0; t < TT; t++) {
        int r = b * TT + t;
        s += g_nll[r];
        cnt += (lab[r] > 0) ? 1.f : 0.f;
    }
    red[b] = s / (cnt + 1e-6f);
    __syncthreads();
    if (b == 0) {
        float a = 0.f;
        for (int i = 0; i < 64; i++) a += red[i];
        out[0] = a / 64.f;
    }
}

// ---------------- host launcher ----------------
extern "C" void kernel_launch(void* const* d_in, const int* in_sizes, int n_in,
                              void* d_out, int out_size)
{
    const float* encode_hidden = (const float*)d_in[0];
    const float* encode_output = (const float*)d_in[1];
    const int*   seq_label     = (const int*)  d_in[3];
    const int*   decoder_input = (const int*)  d_in[4];
    const float* style_emb     = (const float*)d_in[5];
    const float* w_e2d         = (const float*)d_in[6];
    const float* b_e2d         = (const float*)d_in[7];
    const float* attn_W        = (const float*)d_in[8];
    const float* emb_table     = (const float*)d_in[9];
    const float* w_ih          = (const float*)d_in[10];
    const float* w_hh          = (const float*)d_in[11];
    const float* b_ih          = (const float*)d_in[12];
    const float* b_hh          = (const float*)d_in[13];
    const float* proj_w        = (const float*)d_in[14];
    const float* proj_b        = (const float*)d_in[15];
    float* out = (float*)d_out;

    float *p_cat, *p_inp2, *p_gates, *p_emb, *p_xproj, *p_wcomb, *p_biassum, *p_E2;
    cudaGetSymbolAddress((void**)&p_cat,     g_cat);
    cudaGetSymbolAddress((void**)&p_inp2,    g_inp2);
    cudaGetSymbolAddress((void**)&p_gates,   g_gates);
    cudaGetSymbolAddress((void**)&p_emb,     g_emb);
    cudaGetSymbolAddress((void**)&p_xproj,   g_xproj);
    cudaGetSymbolAddress((void**)&p_wcomb,   g_wcomb);
    cudaGetSymbolAddress((void**)&p_biassum, g_biassum);
    cudaGetSymbolAddress((void**)&p_E2,      g_E2);

    // one-time prep
    prep_small_kernel<<<424, 256>>>(encode_hidden, style_emb, b_ih, b_hh);
    wcomb_kernel<<<2048, 1024>>>(w_ih, w_hh);
    embed_kernel<<<BT, 512>>>(decoder_input, emb_table);

    // h0 = cat @ W_e2d^T + b  -> h half of inp2
    gemm_kernel<true, false><<<dim3(8, 1, 1), 256>>>(640,
        p_cat, 640, w_e2d, 640, p_inp2 + 512, 1024, b_e2d, nullptr, 0);

    // xproj = emb @ W_ih_emb^T + (b_ih + b_hh)
    gemm_kernel<true, false><<<dim3(32, 21, 1), 256>>>(512,
        p_emb, 512, w_ih + 512, 1024, p_xproj, 2048, p_biassum, nullptr, 0);

    // E2 = enc @ attn_W^T
    gemm_kernel<true, false><<<dim3(8, 64, 1), 256>>>(512,
        encode_output, 512, attn_W, 512, p_E2, 512, nullptr, nullptr, 0);

    for (int t = 0; t < TT; t++) {
        pwattn_kernel<<<64, 256>>>(encode_output, t);
        // gates += [ctx|h] @ [W_ih_ctx|W_hh]^T  (split-K atomic; pre-inited = xproj[t])
        gemm_kernel<true, true><<<dim3(32, 1, 4), 256>>>(256,
            p_inp2, 1024, p_wcomb, 1024, p_gates, 2048, nullptr, nullptr, 0);
    }
    pw_final_kernel<<<64, 512>>>();

    // loss
    lablogit_kernel<<<168, 256>>>(seq_label, proj_w, proj_b);
    proj_lse_kernel<<<dim3(NTILE, 21), 256>>>(proj_w, proj_b);
    loss_row_kernel<<<BT, 128>>>(seq_label);
    loss_final_kernel<<<1, 64>>>(seq_label, out);
}